// round 1
// baseline (speedup 1.0000x reference)
#include <cuda_runtime.h>

// Problem constants
#define TSTEPS 500
#define BATCH  128
#define WIN    256
#define NFILT  512
#define NCLS   10
#define MROWS  (TSTEPS * BATCH)   // 64000
#define NBF    (BATCH * NFILT)    // 65536

// Scratch (device globals: no runtime allocation allowed)
__device__ float g_proj[TSTEPS * NBF];   // [T, B, F] = 131 MB
__device__ float g_counts[NBF];          // [B, F]

// ----------------------------------------------------------------------------
// Kernel 1: proj = X[M,K] @ W[N,K]^T  (M=64000, N=512, K=256), fp32 SIMT GEMM
// BM=128, BN=128, BK=16, 256 threads, 8x8 per-thread tile
// ----------------------------------------------------------------------------
__global__ __launch_bounds__(256, 2)
void fsnn_gemm(const float* __restrict__ A, const float* __restrict__ Wm) {
    constexpr int BM = 128, BN = 128, BK = 16;
    __shared__ float As[BK][BM + 4];   // As[k][m]
    __shared__ float Bs[BK][BN + 4];   // Bs[k][n]

    const int tid = threadIdx.x;
    const int tx = tid & 15;           // 0..15 -> n
    const int ty = tid >> 4;           // 0..15 -> m
    const long m0 = (long)blockIdx.y * BM;
    const int  n0 = blockIdx.x * BN;

    const float* Ablk = A  + m0 * WIN;
    const float* Wblk = Wm + (long)n0 * WIN;

    float acc[8][8];
#pragma unroll
    for (int i = 0; i < 8; i++)
#pragma unroll
        for (int j = 0; j < 8; j++) acc[i][j] = 0.0f;

    for (int k0 = 0; k0 < WIN; k0 += BK) {
        // Load A tile: 128 rows x 16 cols (2 float4 per thread)
#pragma unroll
        for (int i = 0; i < 2; i++) {
            int id = tid + i * 256;
            int r  = id >> 2;
            int c4 = (id & 3) * 4;
            float4 v = *(const float4*)(Ablk + (long)r * WIN + k0 + c4);
            As[c4 + 0][r] = v.x; As[c4 + 1][r] = v.y;
            As[c4 + 2][r] = v.z; As[c4 + 3][r] = v.w;
        }
        // Load W tile: 128 n-rows x 16 k-cols (2 float4 per thread)
#pragma unroll
        for (int i = 0; i < 2; i++) {
            int id = tid + i * 256;
            int r  = id >> 2;
            int c4 = (id & 3) * 4;
            float4 v = *(const float4*)(Wblk + (long)r * WIN + k0 + c4);
            Bs[c4 + 0][r] = v.x; Bs[c4 + 1][r] = v.y;
            Bs[c4 + 2][r] = v.z; Bs[c4 + 3][r] = v.w;
        }
        __syncthreads();

#pragma unroll
        for (int k = 0; k < BK; k++) {
            // m: 8 contiguous rows at ty*8; n: two float4 granules tx*4 and 64+tx*4
            float4 a0 = *(const float4*)&As[k][ty * 8];
            float4 a1 = *(const float4*)&As[k][ty * 8 + 4];
            float4 b0 = *(const float4*)&Bs[k][tx * 4];
            float4 b1 = *(const float4*)&Bs[k][64 + tx * 4];
            float rm[8] = {a0.x, a0.y, a0.z, a0.w, a1.x, a1.y, a1.z, a1.w};
            float rn[8] = {b0.x, b0.y, b0.z, b0.w, b1.x, b1.y, b1.z, b1.w};
#pragma unroll
            for (int i = 0; i < 8; i++)
#pragma unroll
                for (int j = 0; j < 8; j++)
                    acc[i][j] = fmaf(rm[i], rn[j], acc[i][j]);
        }
        __syncthreads();
    }

    // Write out: rows m0+ty*8+i, cols n0 + {tx*4..+3, 64+tx*4..+3}
    float* Crow = g_proj + m0 * NFILT + n0;
#pragma unroll
    for (int i = 0; i < 8; i++) {
        long roff = (long)(ty * 8 + i) * NFILT;
        float4 v0 = make_float4(acc[i][0], acc[i][1], acc[i][2], acc[i][3]);
        float4 v1 = make_float4(acc[i][4], acc[i][5], acc[i][6], acc[i][7]);
        *(float4*)(Crow + roff + tx * 4)      = v0;
        *(float4*)(Crow + roff + 64 + tx * 4) = v1;
    }
}

// ----------------------------------------------------------------------------
// Kernel 2: LIF scan. One thread per (b,f) trajectory; 500 sequential steps.
// trace = 0.95*trace + p; u = 0.9*u + trace; spike if u > 1 -> reset, count++
// ----------------------------------------------------------------------------
__global__ __launch_bounds__(256)
void fsnn_scan() {
    const int idx = blockIdx.x * blockDim.x + threadIdx.x;   // 0..65535
    const float* __restrict__ p = g_proj + idx;

    float u = 0.0f, tr = 0.0f, cnt = 0.0f;
#pragma unroll 10
    for (int t = 0; t < TSTEPS; t++) {
        float x = p[t * NBF];
        tr = 0.95f * tr + x;
        u  = 0.9f  * u  + tr;
        if (u > 1.0f) { cnt += 1.0f; u = 0.0f; }
    }
    g_counts[idx] = cnt;
}

// ----------------------------------------------------------------------------
// Kernel 3: decoder. out[b][c] = counts[b,:] . dec_w[c,:] + dec_b[c]
// One block per b, one warp per class.
// ----------------------------------------------------------------------------
__global__ __launch_bounds__(320)
void fsnn_decoder(const float* __restrict__ dec_w,
                  const float* __restrict__ dec_b,
                  float* __restrict__ out) {
    const int b    = blockIdx.x;
    const int lane = threadIdx.x & 31;
    const int c    = threadIdx.x >> 5;     // 0..9
    if (c >= NCLS) return;

    const float* crow = g_counts + b * NFILT;
    const float* wrow = dec_w + c * NFILT;
    float s = 0.0f;
#pragma unroll 4
    for (int f = lane; f < NFILT; f += 32)
        s = fmaf(crow[f], wrow[f], s);
#pragma unroll
    for (int o = 16; o; o >>= 1) s += __shfl_xor_sync(0xFFFFFFFFu, s, o);
    if (lane == 0) out[b * NCLS + c] = s + dec_b[c];
}

// ----------------------------------------------------------------------------
extern "C" void kernel_launch(void* const* d_in, const int* in_sizes, int n_in,
                              void* d_out, int out_size) {
    const float* x     = (const float*)d_in[0];   // [500,128,256]
    const float* w     = (const float*)d_in[1];   // [512,256]
    const float* dec_w = (const float*)d_in[2];   // [10,512]
    const float* dec_b = (const float*)d_in[3];   // [10]
    float* out = (float*)d_out;                   // [128,10]

    dim3 ggrid(NFILT / 128, MROWS / 128);         // (4, 500)
    fsnn_gemm<<<ggrid, 256>>>(x, w);
    fsnn_scan<<<NBF / 256, 256>>>();
    fsnn_decoder<<<BATCH, 320>>>(dec_w, dec_b, out);
}